// round 13
// baseline (speedup 1.0000x reference)
#include <cuda_runtime.h>
#include <cstdint>

#define S_LEN 8192
#define C_LEN 24
#define E_DIM 512
#define H_DIM 1024
#define R_DIM 256
#define L_DIM 50
#define GATE_W (4*H_DIM)       // 4096
#define XCAT_DIM (E_DIM+R_DIM) // 768
#define RG 128                 // persistent CTAs for recurrence
#define SENT 0x7FC00001u       // NaN-payload sentinel; real h in (-1,1) never equals it
#define RT 384                 // recurrence threads: 8 GEMV warps + 4 poller warps

// ---------------- static scratch (allocation-free rule) ----------------
__device__ float d_X[(size_t)S_LEN*GATE_W];       // precomputed x-gates + bias
__device__ float d_Hs[(size_t)S_LEN*H_DIM];       // word-LSTM hidden states (sentinel-filled)
__device__ float d_gates[(size_t)S_LEN*4*R_DIM];  // char-LSTM gate scratch
__device__ float d_xcat[(size_t)S_LEN*XCAT_DIM];  // [embed | char_rep]
__device__ float d_hchar[(size_t)S_LEN*R_DIM];
__device__ float d_cchar[(size_t)S_LEN*R_DIM];

__device__ __forceinline__ float sigmf(float x){ return 1.f/(1.f+__expf(-x)); }
__device__ __forceinline__ float tanh_fast(float x){
    float e = __expf(-2.f*x);                  // overflow-safe: e=inf -> -1, e=0 -> 1
    return __fdividef(2.f, 1.f + e) - 1.f;
}

// packed f32x2 FMA (FFMA2) — PTX-only path, 2 fp32 MACs per issue slot
__device__ __forceinline__ unsigned long long ffma2(
    unsigned long long a, unsigned long long b, unsigned long long c)
{
    unsigned long long d;
    asm("fma.rn.f32x2 %0, %1, %2, %3;" : "=l"(d) : "l"(a), "l"(b), "l"(c));
    return d;
}
__device__ __forceinline__ unsigned long long packf2(float a){
    unsigned long long d;
    unsigned u = __float_as_uint(a);
    asm("mov.b64 %0, {%1, %1};" : "=l"(d) : "r"(u));
    return d;
}

// ---------------- init: sentinel-fill d_Hs, zero char states ----------------
__global__ void init_kernel()
{
    int i = blockIdx.x*blockDim.x + threadIdx.x;
    int nth = gridDim.x*blockDim.x;
    uint4* p = (uint4*)d_Hs;
    int n4 = (S_LEN*H_DIM)/4;
    uint4 sv = make_uint4(SENT,SENT,SENT,SENT);
    for (int k = i; k < n4; k += nth) p[k] = sv;
    int n = S_LEN*R_DIM;
    for (int k = i; k < n; k += nth){
        d_hchar[k] = 0.f;
        d_cchar[k] = 0.f;
    }
}

// ---------------- FFMA2 tiled GEMM: C[M,N] = A[M,K] * B[N,K]^T (+bias[N]) ----------------
// 128x128 CTA tile, 16-deep K panels, 8x8 micro-tile per thread (256 threads).
__global__ __launch_bounds__(256, 2) void sgemm128(
    const float* __restrict__ A, const float* __restrict__ B,
    float* __restrict__ C, const float* __restrict__ bias,
    int M, int N, int K)
{
    __shared__ float As[16][132];
    __shared__ float Bs[16][132];
    const int bm = blockIdx.y*128, bn = blockIdx.x*128;
    const int tid = threadIdx.x;
    const int tx = tid & 15, ty = tid >> 4;
    const int lrow = tid >> 1, lcol = (tid & 1) << 3;

    unsigned long long acc2[8][4];
    #pragma unroll
    for (int i=0;i<8;i++)
        #pragma unroll
        for (int j=0;j<4;j++) acc2[i][j] = 0ull;

    const float* Ag = A + (size_t)(bm+lrow)*K + lcol;
    const float* Bg = B + (size_t)(bn+lrow)*K + lcol;

    for (int k0 = 0; k0 < K; k0 += 16){
        float4 a0 = *(const float4*)(Ag + k0);
        float4 a1 = *(const float4*)(Ag + k0 + 4);
        float4 b0 = *(const float4*)(Bg + k0);
        float4 b1 = *(const float4*)(Bg + k0 + 4);
        As[lcol+0][lrow]=a0.x; As[lcol+1][lrow]=a0.y; As[lcol+2][lrow]=a0.z; As[lcol+3][lrow]=a0.w;
        As[lcol+4][lrow]=a1.x; As[lcol+5][lrow]=a1.y; As[lcol+6][lrow]=a1.z; As[lcol+7][lrow]=a1.w;
        Bs[lcol+0][lrow]=b0.x; Bs[lcol+1][lrow]=b0.y; Bs[lcol+2][lrow]=b0.z; Bs[lcol+3][lrow]=b0.w;
        Bs[lcol+4][lrow]=b1.x; Bs[lcol+5][lrow]=b1.y; Bs[lcol+6][lrow]=b1.z; Bs[lcol+7][lrow]=b1.w;
        __syncthreads();
        #pragma unroll
        for (int kk=0;kk<16;kk++){
            float4 av0 = *(const float4*)&As[kk][ty*8];
            float4 av1 = *(const float4*)&As[kk][ty*8+4];
            float a[8] = {av0.x,av0.y,av0.z,av0.w,av1.x,av1.y,av1.z,av1.w};
            unsigned long long b2[4];
            #pragma unroll
            for (int j=0;j<4;j++){
                float2 bv = *(const float2*)&Bs[kk][tx*2 + 32*j];
                b2[j] = *reinterpret_cast<unsigned long long*>(&bv);
            }
            #pragma unroll
            for (int i=0;i<8;i++){
                unsigned long long aa = packf2(a[i]);
                #pragma unroll
                for (int j=0;j<4;j++)
                    acc2[i][j] = ffma2(aa, b2[j], acc2[i][j]);
            }
        }
        __syncthreads();
    }

    #pragma unroll
    for (int i=0;i<8;i++){
        int row = bm + ty*8 + i;
        #pragma unroll
        for (int j=0;j<4;j++){
            int col = bn + tx*2 + 32*j;
            float2 p = *reinterpret_cast<float2*>(&acc2[i][j]);
            if (bias){ p.x += bias[col]; p.y += bias[col+1]; }
            *(float2*)&C[(size_t)row*N + col] = p;
        }
    }
}

// ---------------- char-LSTM pointwise update (after gates GEMM) ----------------
__global__ __launch_bounds__(256) void char_update(
    const float* __restrict__ chars,
    const float* __restrict__ Wc_ih,
    const float* __restrict__ bc,
    int step)
{
    int idx = blockIdx.x*blockDim.x + threadIdx.x;
    if (idx >= S_LEN*R_DIM) return;
    int r = idx & (R_DIM-1);
    int s = idx >> 8;
    float x = chars[s*C_LEN + step];
    const float* g = d_gates + (size_t)s*4*R_DIM;
    float gi = g[r]           + Wc_ih[r]          *x + bc[r];
    float gf = g[R_DIM+r]     + Wc_ih[R_DIM+r]    *x + bc[R_DIM+r];
    float gg = g[2*R_DIM+r]   + Wc_ih[2*R_DIM+r]  *x + bc[2*R_DIM+r];
    float go = g[3*R_DIM+r]   + Wc_ih[3*R_DIM+r]  *x + bc[3*R_DIM+r];
    float c = d_cchar[idx];
    c = sigmf(gf)*c + sigmf(gi)*tanh_fast(gg);
    d_cchar[idx] = c;
    d_hchar[idx] = sigmf(go)*tanh_fast(c);
}

// ---------------- embed gather + concat with char_rep ----------------
__global__ __launch_bounds__(256) void gather_concat(
    const int* __restrict__ sentence,
    const float* __restrict__ embed)
{
    int idx = blockIdx.x*blockDim.x + threadIdx.x;
    if (idx >= S_LEN*XCAT_DIM) return;
    int c = idx % XCAT_DIM;
    int s = idx / XCAT_DIM;
    d_xcat[idx] = (c < E_DIM)
        ? embed[(size_t)sentence[s]*E_DIM + c]
        : d_hchar[s*R_DIM + (c - E_DIM)];
}

// ---------------- persistent word-LSTM recurrence (R12 + 4 poller warps) ----------------
// 128 CTAs x 384 threads. Warps 0-7: GEMV+epilogue for h unit (cta*8+w), weights
// in regs. Warps 8-11: pollers, each lane owns 2 chunks, SERIALIZED load-test-
// store sweep (scoreboard-paced probing — the validated rate limiter). Halving
// chunks-per-lane halves worst-case detection latency (1040 -> ~520 cyc) at
// ~1000 B/cyc chip-wide poll traffic (16% of LTS cap).
__global__ __launch_bounds__(RT, 1) void word_recur(const float* __restrict__ Whh)
{
    const int cta  = blockIdx.x;
    const int w    = threadIdx.x >> 5;
    const int lane = threadIdx.x & 31;

    __shared__ float hsm[2][H_DIM];   // parity double-buffered h

    for (int i = threadIdx.x; i < H_DIM; i += RT) hsm[0][i] = 0.f;  // h(-1)=0

    // GEMV warps: weights for rows j_g = g*H_DIM + cta*8 + w
    ulonglong2 wq[4][8];
    float xv[4] = {0.f,0.f,0.f,0.f};
    float cstate = 0.f;
    if (w < 8){
        #pragma unroll
        for (int g=0; g<4; g++){
            const ulonglong2* W = (const ulonglong2*)(Whh + (size_t)(g*H_DIM + cta*8 + w)*H_DIM);
            #pragma unroll
            for (int i=0;i<8;i++) wq[g][i] = W[lane + 32*i];
        }
        if (lane == 0){
            #pragma unroll
            for (int g=0; g<4; g++) xv[g] = d_X[g*H_DIM + cta*8 + w];
        }
    }
    __syncthreads();

    for (int t = 0; t < S_LEN; t++){
        if (w < 8){
            // ---- GEMV over hsm[t&1] ----
            const float4* h4 = (const float4*)hsm[t & 1];
            unsigned long long accA[4] = {0ull,0ull,0ull,0ull};
            unsigned long long accB[4] = {0ull,0ull,0ull,0ull};
            #pragma unroll
            for (int i=0;i<8;i++){
                float4 hv4 = h4[lane + 32*i];
                ulonglong2 hu = *reinterpret_cast<ulonglong2*>(&hv4);
                #pragma unroll
                for (int g=0; g<4; g++){
                    accA[g] = ffma2(hu.x, wq[g][i].x, accA[g]);
                    accB[g] = ffma2(hu.y, wq[g][i].y, accB[g]);
                }
            }
            float s[4];
            #pragma unroll
            for (int g=0; g<4; g++){
                float2 fa = *reinterpret_cast<float2*>(&accA[g]);
                float2 fb = *reinterpret_cast<float2*>(&accB[g]);
                s[g] = (fa.x + fa.y) + (fb.x + fb.y);
            }
            #pragma unroll
            for (int m=16;m>0;m>>=1){
                #pragma unroll
                for (int g=0; g<4; g++)
                    s[g] += __shfl_down_sync(0xffffffffu, s[g], m);
            }
            // ---- epilogue + publish (lane 0): the h store IS the flag ----
            if (lane == 0){
                float gi = s[0]+xv[0], gf = s[1]+xv[1], gg = s[2]+xv[2], go = s[3]+xv[3];
                float c = sigmf(gf)*cstate + sigmf(gi)*tanh_fast(gg);
                cstate = c;
                float hv = sigmf(go)*tanh_fast(c);
                float* dst = d_Hs + (size_t)t*H_DIM + cta*8 + w;
                asm volatile("st.global.cg.f32 [%0], %1;" :: "l"(dst), "f"(hv) : "memory");
                if (t + 1 < S_LEN){
                    #pragma unroll
                    for (int g=0; g<4; g++)
                        xv[g] = __ldcs(&d_X[(size_t)(t+1)*GATE_W + g*H_DIM + cta*8 + w]);
                }
            }
        } else {
            // ---- pollers (warps 8-11): SERIALIZED sweep, 2 chunks per lane ----
            const int pw = w - 8;                     // 0..3, each covers 64 uint4
            const uint4* hrow = (const uint4*)(d_Hs + (size_t)t*H_DIM);
            uint4* dst4 = (uint4*)hsm[(t+1) & 1];
            unsigned pend = 0x3u;                     // 2 chunks of 16B per lane
            do {
                #pragma unroll
                for (int k = 0; k < 2; k++){
                    if (pend & (1u<<k)){
                        int idx = pw*64 + k*32 + lane;
                        uint4 v;
                        asm volatile("ld.global.cg.v4.u32 {%0,%1,%2,%3}, [%4];"
                            : "=r"(v.x), "=r"(v.y), "=r"(v.z), "=r"(v.w)
                            : "l"(hrow + idx) : "memory");
                        if (v.x != SENT && v.y != SENT && v.z != SENT && v.w != SENT){
                            dst4[idx] = v;
                            pend &= ~(1u<<k);
                        }
                    }
                }
            } while (__ballot_sync(0xffffffffu, pend != 0u));
        }
        __syncthreads();   // hsm[(t+1)&1] complete
    }
}

// ---------------- output layer + log_softmax ----------------
__global__ __launch_bounds__(128) void out_kernel(
    const float* __restrict__ Wout,
    const float* __restrict__ bout,
    float* __restrict__ out)
{
    int s = blockIdx.x;
    __shared__ float hrow[H_DIM];
    __shared__ float e[64];
    __shared__ float s_lse;
    int tid = threadIdx.x;

    const float4* Hs4 = (const float4*)(d_Hs + (size_t)s*H_DIM);
    ((float4*)hrow)[tid*2]   = Hs4[tid*2];
    ((float4*)hrow)[tid*2+1] = Hs4[tid*2+1];
    __syncthreads();

    int warp = tid >> 5, lane = tid & 31;
    for (int l = warp; l < L_DIM; l += 4){
        const float* wr = Wout + (size_t)l*H_DIM;
        float sum = 0.f;
        for (int k = lane; k < H_DIM; k += 32) sum = fmaf(hrow[k], wr[k], sum);
        #pragma unroll
        for (int m=16;m>0;m>>=1) sum += __shfl_xor_sync(0xffffffffu, sum, m);
        if (lane == 0) e[l] = sum + bout[l];
    }
    __syncthreads();

    if (tid < 32){
        float mx = -1e30f;
        for (int l = tid; l < L_DIM; l += 32) mx = fmaxf(mx, e[l]);
        #pragma unroll
        for (int m=16;m>0;m>>=1) mx = fmaxf(mx, __shfl_xor_sync(0xffffffffu, mx, m));
        float sum = 0.f;
        for (int l = tid; l < L_DIM; l += 32) sum += __expf(e[l]-mx);
        #pragma unroll
        for (int m=16;m>0;m>>=1) sum += __shfl_xor_sync(0xffffffffu, sum, m);
        if (tid == 0) s_lse = mx + logf(sum);
    }
    __syncthreads();

    for (int l = tid; l < L_DIM; l += 128)
        out[(size_t)s*L_DIM + l] = e[l] - s_lse;
}

// ---------------- launch ----------------
extern "C" void kernel_launch(void* const* d_in, const int* in_sizes, int n_in,
                              void* d_out, int out_size)
{
    const int*   sentence = (const int*)  d_in[0];
    const float* chars    = (const float*)d_in[1];
    const float* embed    = (const float*)d_in[2];
    const float* Wc_ih    = (const float*)d_in[3];
    const float* Wc_hh    = (const float*)d_in[4];
    const float* bc       = (const float*)d_in[5];
    const float* Ww_ih    = (const float*)d_in[6];
    const float* Ww_hh    = (const float*)d_in[7];
    const float* bw       = (const float*)d_in[8];
    const float* Wout     = (const float*)d_in[9];
    const float* bout     = (const float*)d_in[10];
    float* out = (float*)d_out;

    float *pX, *pGates, *pXcat, *pHchar;
    cudaGetSymbolAddress((void**)&pX,     d_X);
    cudaGetSymbolAddress((void**)&pGates, d_gates);
    cudaGetSymbolAddress((void**)&pXcat,  d_xcat);
    cudaGetSymbolAddress((void**)&pHchar, d_hchar);

    init_kernel<<<2048, 256>>>();

    // char-level LSTM: gates GEMM (FFMA2) + pointwise, 24 steps
    dim3 gChar(4*R_DIM/128, S_LEN/128);   // (8, 64)
    int pwBlocks = (S_LEN*R_DIM + 255)/256;
    for (int step = 0; step < C_LEN; step++){
        sgemm128<<<gChar, 256>>>(pHchar, Wc_hh, pGates, nullptr,
                                 S_LEN, 4*R_DIM, R_DIM);
        char_update<<<pwBlocks, 256>>>(chars, Wc_ih, bc, step);
    }

    // concat [embed(sentence) | char_rep]
    int gcBlocks = (S_LEN*XCAT_DIM + 255)/256;
    gather_concat<<<gcBlocks, 256>>>(sentence, embed);

    // precompute word-LSTM x-gates: X = xcat @ Ww_ih^T + bw
    dim3 gPre(GATE_W/128, S_LEN/128);     // (32, 64)
    sgemm128<<<gPre, 256>>>(pXcat, Ww_ih, pX, bw,
                            S_LEN, GATE_W, XCAT_DIM);

    // sequential word-LSTM recurrence (serialized poller, 4 poller warps)
    word_recur<<<RG, RT>>>(Ww_hh);

    // output layer + log_softmax
    out_kernel<<<S_LEN, 128>>>(Wout, bout, out);
}

// round 14
// speedup vs baseline: 1.0765x; 1.0765x over previous
#include <cuda_runtime.h>
#include <cstdint>

#define S_LEN 8192
#define C_LEN 24
#define E_DIM 512
#define H_DIM 1024
#define R_DIM 256
#define L_DIM 50
#define GATE_W (4*H_DIM)       // 4096
#define XCAT_DIM (E_DIM+R_DIM) // 768
#define RG 128                 // persistent CTAs for recurrence
#define SENT 0x7FC00001u       // NaN-payload sentinel; real h in (-1,1) never equals it
#define RT 384                 // recurrence threads: 8 GEMV warps + 4 poller warps

// ---------------- static scratch (allocation-free rule) ----------------
__device__ float d_X[(size_t)S_LEN*GATE_W];       // precomputed x-gates + bias
__device__ float d_Hs[(size_t)S_LEN*H_DIM];       // word-LSTM hidden states (sentinel-filled)
__device__ float d_gates[(size_t)S_LEN*4*R_DIM];  // char-LSTM gate scratch
__device__ float d_xcat[(size_t)S_LEN*XCAT_DIM];  // [embed | char_rep]
__device__ float d_hchar[(size_t)S_LEN*R_DIM];
__device__ float d_cchar[(size_t)S_LEN*R_DIM];

__device__ __forceinline__ float sigmf(float x){ return 1.f/(1.f+__expf(-x)); }
__device__ __forceinline__ float tanh_fast(float x){
    float e = __expf(-2.f*x);                  // overflow-safe: e=inf -> -1, e=0 -> 1
    return __fdividef(2.f, 1.f + e) - 1.f;
}

// packed f32x2 FMA (FFMA2) — PTX-only path, 2 fp32 MACs per issue slot
__device__ __forceinline__ unsigned long long ffma2(
    unsigned long long a, unsigned long long b, unsigned long long c)
{
    unsigned long long d;
    asm("fma.rn.f32x2 %0, %1, %2, %3;" : "=l"(d) : "l"(a), "l"(b), "l"(c));
    return d;
}
__device__ __forceinline__ unsigned long long packf2(float a){
    unsigned long long d;
    unsigned u = __float_as_uint(a);
    asm("mov.b64 %0, {%1, %1};" : "=l"(d) : "r"(u));
    return d;
}

// ---------------- init: sentinel-fill d_Hs, zero char states ----------------
__global__ void init_kernel()
{
    int i = blockIdx.x*blockDim.x + threadIdx.x;
    int nth = gridDim.x*blockDim.x;
    uint4* p = (uint4*)d_Hs;
    int n4 = (S_LEN*H_DIM)/4;
    uint4 sv = make_uint4(SENT,SENT,SENT,SENT);
    for (int k = i; k < n4; k += nth) p[k] = sv;
    int n = S_LEN*R_DIM;
    for (int k = i; k < n; k += nth){
        d_hchar[k] = 0.f;
        d_cchar[k] = 0.f;
    }
}

// ---------------- FFMA2 tiled GEMM: C[M,N] = A[M,K] * B[N,K]^T (+bias[N]) ----------------
// 128x128 CTA tile, 16-deep K panels, 8x8 micro-tile per thread (256 threads).
__global__ __launch_bounds__(256, 2) void sgemm128(
    const float* __restrict__ A, const float* __restrict__ B,
    float* __restrict__ C, const float* __restrict__ bias,
    int M, int N, int K)
{
    __shared__ float As[16][132];
    __shared__ float Bs[16][132];
    const int bm = blockIdx.y*128, bn = blockIdx.x*128;
    const int tid = threadIdx.x;
    const int tx = tid & 15, ty = tid >> 4;
    const int lrow = tid >> 1, lcol = (tid & 1) << 3;

    unsigned long long acc2[8][4];
    #pragma unroll
    for (int i=0;i<8;i++)
        #pragma unroll
        for (int j=0;j<4;j++) acc2[i][j] = 0ull;

    const float* Ag = A + (size_t)(bm+lrow)*K + lcol;
    const float* Bg = B + (size_t)(bn+lrow)*K + lcol;

    for (int k0 = 0; k0 < K; k0 += 16){
        float4 a0 = *(const float4*)(Ag + k0);
        float4 a1 = *(const float4*)(Ag + k0 + 4);
        float4 b0 = *(const float4*)(Bg + k0);
        float4 b1 = *(const float4*)(Bg + k0 + 4);
        As[lcol+0][lrow]=a0.x; As[lcol+1][lrow]=a0.y; As[lcol+2][lrow]=a0.z; As[lcol+3][lrow]=a0.w;
        As[lcol+4][lrow]=a1.x; As[lcol+5][lrow]=a1.y; As[lcol+6][lrow]=a1.z; As[lcol+7][lrow]=a1.w;
        Bs[lcol+0][lrow]=b0.x; Bs[lcol+1][lrow]=b0.y; Bs[lcol+2][lrow]=b0.z; Bs[lcol+3][lrow]=b0.w;
        Bs[lcol+4][lrow]=b1.x; Bs[lcol+5][lrow]=b1.y; Bs[lcol+6][lrow]=b1.z; Bs[lcol+7][lrow]=b1.w;
        __syncthreads();
        #pragma unroll
        for (int kk=0;kk<16;kk++){
            float4 av0 = *(const float4*)&As[kk][ty*8];
            float4 av1 = *(const float4*)&As[kk][ty*8+4];
            float a[8] = {av0.x,av0.y,av0.z,av0.w,av1.x,av1.y,av1.z,av1.w};
            unsigned long long b2[4];
            #pragma unroll
            for (int j=0;j<4;j++){
                float2 bv = *(const float2*)&Bs[kk][tx*2 + 32*j];
                b2[j] = *reinterpret_cast<unsigned long long*>(&bv);
            }
            #pragma unroll
            for (int i=0;i<8;i++){
                unsigned long long aa = packf2(a[i]);
                #pragma unroll
                for (int j=0;j<4;j++)
                    acc2[i][j] = ffma2(aa, b2[j], acc2[i][j]);
            }
        }
        __syncthreads();
    }

    #pragma unroll
    for (int i=0;i<8;i++){
        int row = bm + ty*8 + i;
        #pragma unroll
        for (int j=0;j<4;j++){
            int col = bn + tx*2 + 32*j;
            float2 p = *reinterpret_cast<float2*>(&acc2[i][j]);
            if (bias){ p.x += bias[col]; p.y += bias[col+1]; }
            *(float2*)&C[(size_t)row*N + col] = p;
        }
    }
}

// ---------------- char-LSTM pointwise update (after gates GEMM) ----------------
__global__ __launch_bounds__(256) void char_update(
    const float* __restrict__ chars,
    const float* __restrict__ Wc_ih,
    const float* __restrict__ bc,
    int step)
{
    int idx = blockIdx.x*blockDim.x + threadIdx.x;
    if (idx >= S_LEN*R_DIM) return;
    int r = idx & (R_DIM-1);
    int s = idx >> 8;
    float x = chars[s*C_LEN + step];
    const float* g = d_gates + (size_t)s*4*R_DIM;
    float gi = g[r]           + Wc_ih[r]          *x + bc[r];
    float gf = g[R_DIM+r]     + Wc_ih[R_DIM+r]    *x + bc[R_DIM+r];
    float gg = g[2*R_DIM+r]   + Wc_ih[2*R_DIM+r]  *x + bc[2*R_DIM+r];
    float go = g[3*R_DIM+r]   + Wc_ih[3*R_DIM+r]  *x + bc[3*R_DIM+r];
    float c = d_cchar[idx];
    c = sigmf(gf)*c + sigmf(gi)*tanh_fast(gg);
    d_cchar[idx] = c;
    d_hchar[idx] = sigmf(go)*tanh_fast(c);
}

// ---------------- embed gather + concat with char_rep ----------------
__global__ __launch_bounds__(256) void gather_concat(
    const int* __restrict__ sentence,
    const float* __restrict__ embed)
{
    int idx = blockIdx.x*blockDim.x + threadIdx.x;
    if (idx >= S_LEN*XCAT_DIM) return;
    int c = idx % XCAT_DIM;
    int s = idx / XCAT_DIM;
    d_xcat[idx] = (c < E_DIM)
        ? embed[(size_t)sentence[s]*E_DIM + c]
        : d_hchar[s*R_DIM + (c - E_DIM)];
}

// ---------------- persistent word-LSTM recurrence (R12 + 4 poller warps) ----------------
// 128 CTAs x 384 threads. Warps 0-7: GEMV+epilogue for h unit (cta*8+w), weights
// in regs. Warps 8-11: pollers, each lane owns 2 chunks, SERIALIZED load-test-
// store sweep (scoreboard-paced probing — the validated rate limiter). Halving
// chunks-per-lane halves worst-case detection latency (1040 -> ~520 cyc) at
// ~1000 B/cyc chip-wide poll traffic (16% of LTS cap).
__global__ __launch_bounds__(RT, 1) void word_recur(const float* __restrict__ Whh)
{
    const int cta  = blockIdx.x;
    const int w    = threadIdx.x >> 5;
    const int lane = threadIdx.x & 31;

    __shared__ float hsm[2][H_DIM];   // parity double-buffered h

    for (int i = threadIdx.x; i < H_DIM; i += RT) hsm[0][i] = 0.f;  // h(-1)=0

    // GEMV warps: weights for rows j_g = g*H_DIM + cta*8 + w
    ulonglong2 wq[4][8];
    float xv[4] = {0.f,0.f,0.f,0.f};
    float cstate = 0.f;
    if (w < 8){
        #pragma unroll
        for (int g=0; g<4; g++){
            const ulonglong2* W = (const ulonglong2*)(Whh + (size_t)(g*H_DIM + cta*8 + w)*H_DIM);
            #pragma unroll
            for (int i=0;i<8;i++) wq[g][i] = W[lane + 32*i];
        }
        if (lane == 0){
            #pragma unroll
            for (int g=0; g<4; g++) xv[g] = d_X[g*H_DIM + cta*8 + w];
        }
    }
    __syncthreads();

    for (int t = 0; t < S_LEN; t++){
        if (w < 8){
            // ---- GEMV over hsm[t&1] ----
            const float4* h4 = (const float4*)hsm[t & 1];
            unsigned long long accA[4] = {0ull,0ull,0ull,0ull};
            unsigned long long accB[4] = {0ull,0ull,0ull,0ull};
            #pragma unroll
            for (int i=0;i<8;i++){
                float4 hv4 = h4[lane + 32*i];
                ulonglong2 hu = *reinterpret_cast<ulonglong2*>(&hv4);
                #pragma unroll
                for (int g=0; g<4; g++){
                    accA[g] = ffma2(hu.x, wq[g][i].x, accA[g]);
                    accB[g] = ffma2(hu.y, wq[g][i].y, accB[g]);
                }
            }
            float s[4];
            #pragma unroll
            for (int g=0; g<4; g++){
                float2 fa = *reinterpret_cast<float2*>(&accA[g]);
                float2 fb = *reinterpret_cast<float2*>(&accB[g]);
                s[g] = (fa.x + fa.y) + (fb.x + fb.y);
            }
            #pragma unroll
            for (int m=16;m>0;m>>=1){
                #pragma unroll
                for (int g=0; g<4; g++)
                    s[g] += __shfl_down_sync(0xffffffffu, s[g], m);
            }
            // ---- epilogue + publish (lane 0): the h store IS the flag ----
            if (lane == 0){
                float gi = s[0]+xv[0], gf = s[1]+xv[1], gg = s[2]+xv[2], go = s[3]+xv[3];
                float c = sigmf(gf)*cstate + sigmf(gi)*tanh_fast(gg);
                cstate = c;
                float hv = sigmf(go)*tanh_fast(c);
                float* dst = d_Hs + (size_t)t*H_DIM + cta*8 + w;
                asm volatile("st.global.cg.f32 [%0], %1;" :: "l"(dst), "f"(hv) : "memory");
                if (t + 1 < S_LEN){
                    #pragma unroll
                    for (int g=0; g<4; g++)
                        xv[g] = __ldcs(&d_X[(size_t)(t+1)*GATE_W + g*H_DIM + cta*8 + w]);
                }
            }
        } else {
            // ---- pollers (warps 8-11): SERIALIZED sweep, 2 chunks per lane ----
            const int pw = w - 8;                     // 0..3, each covers 64 uint4
            const uint4* hrow = (const uint4*)(d_Hs + (size_t)t*H_DIM);
            uint4* dst4 = (uint4*)hsm[(t+1) & 1];
            unsigned pend = 0x3u;                     // 2 chunks of 16B per lane
            do {
                #pragma unroll
                for (int k = 0; k < 2; k++){
                    if (pend & (1u<<k)){
                        int idx = pw*64 + k*32 + lane;
                        uint4 v;
                        asm volatile("ld.global.cg.v4.u32 {%0,%1,%2,%3}, [%4];"
                            : "=r"(v.x), "=r"(v.y), "=r"(v.z), "=r"(v.w)
                            : "l"(hrow + idx) : "memory");
                        if (v.x != SENT && v.y != SENT && v.z != SENT && v.w != SENT){
                            dst4[idx] = v;
                            pend &= ~(1u<<k);
                        }
                    }
                }
            } while (__ballot_sync(0xffffffffu, pend != 0u));
        }
        __syncthreads();   // hsm[(t+1)&1] complete
    }
}

// ---------------- output layer + log_softmax ----------------
__global__ __launch_bounds__(128) void out_kernel(
    const float* __restrict__ Wout,
    const float* __restrict__ bout,
    float* __restrict__ out)
{
    int s = blockIdx.x;
    __shared__ float hrow[H_DIM];
    __shared__ float e[64];
    __shared__ float s_lse;
    int tid = threadIdx.x;

    const float4* Hs4 = (const float4*)(d_Hs + (size_t)s*H_DIM);
    ((float4*)hrow)[tid*2]   = Hs4[tid*2];
    ((float4*)hrow)[tid*2+1] = Hs4[tid*2+1];
    __syncthreads();

    int warp = tid >> 5, lane = tid & 31;
    for (int l = warp; l < L_DIM; l += 4){
        const float* wr = Wout + (size_t)l*H_DIM;
        float sum = 0.f;
        for (int k = lane; k < H_DIM; k += 32) sum = fmaf(hrow[k], wr[k], sum);
        #pragma unroll
        for (int m=16;m>0;m>>=1) sum += __shfl_xor_sync(0xffffffffu, sum, m);
        if (lane == 0) e[l] = sum + bout[l];
    }
    __syncthreads();

    if (tid < 32){
        float mx = -1e30f;
        for (int l = tid; l < L_DIM; l += 32) mx = fmaxf(mx, e[l]);
        #pragma unroll
        for (int m=16;m>0;m>>=1) mx = fmaxf(mx, __shfl_xor_sync(0xffffffffu, mx, m));
        float sum = 0.f;
        for (int l = tid; l < L_DIM; l += 32) sum += __expf(e[l]-mx);
        #pragma unroll
        for (int m=16;m>0;m>>=1) sum += __shfl_xor_sync(0xffffffffu, sum, m);
        if (tid == 0) s_lse = mx + logf(sum);
    }
    __syncthreads();

    for (int l = tid; l < L_DIM; l += 128)
        out[(size_t)s*L_DIM + l] = e[l] - s_lse;
}

// ---------------- launch ----------------
extern "C" void kernel_launch(void* const* d_in, const int* in_sizes, int n_in,
                              void* d_out, int out_size)
{
    const int*   sentence = (const int*)  d_in[0];
    const float* chars    = (const float*)d_in[1];
    const float* embed    = (const float*)d_in[2];
    const float* Wc_ih    = (const float*)d_in[3];
    const float* Wc_hh    = (const float*)d_in[4];
    const float* bc       = (const float*)d_in[5];
    const float* Ww_ih    = (const float*)d_in[6];
    const float* Ww_hh    = (const float*)d_in[7];
    const float* bw       = (const float*)d_in[8];
    const float* Wout     = (const float*)d_in[9];
    const float* bout     = (const float*)d_in[10];
    float* out = (float*)d_out;

    float *pX, *pGates, *pXcat, *pHchar;
    cudaGetSymbolAddress((void**)&pX,     d_X);
    cudaGetSymbolAddress((void**)&pGates, d_gates);
    cudaGetSymbolAddress((void**)&pXcat,  d_xcat);
    cudaGetSymbolAddress((void**)&pHchar, d_hchar);

    init_kernel<<<2048, 256>>>();

    // char-level LSTM: gates GEMM (FFMA2) + pointwise, 24 steps
    dim3 gChar(4*R_DIM/128, S_LEN/128);   // (8, 64)
    int pwBlocks = (S_LEN*R_DIM + 255)/256;
    for (int step = 0; step < C_LEN; step++){
        sgemm128<<<gChar, 256>>>(pHchar, Wc_hh, pGates, nullptr,
                                 S_LEN, 4*R_DIM, R_DIM);
        char_update<<<pwBlocks, 256>>>(chars, Wc_ih, bc, step);
    }

    // concat [embed(sentence) | char_rep]
    int gcBlocks = (S_LEN*XCAT_DIM + 255)/256;
    gather_concat<<<gcBlocks, 256>>>(sentence, embed);

    // precompute word-LSTM x-gates: X = xcat @ Ww_ih^T + bw
    dim3 gPre(GATE_W/128, S_LEN/128);     // (32, 64)
    sgemm128<<<gPre, 256>>>(pXcat, Ww_ih, pX, bw,
                            S_LEN, GATE_W, XCAT_DIM);

    // sequential word-LSTM recurrence (serialized poller, 4 poller warps)
    word_recur<<<RG, RT>>>(Ww_hh);

    // output layer + log_softmax
    out_kernel<<<S_LEN, 128>>>(Wout, bout, out);
}

// round 15
// speedup vs baseline: 1.0812x; 1.0044x over previous
#include <cuda_runtime.h>
#include <cstdint>

#define S_LEN 8192
#define C_LEN 24
#define E_DIM 512
#define H_DIM 1024
#define R_DIM 256
#define L_DIM 50
#define GATE_W (4*H_DIM)       // 4096
#define XCAT_DIM (E_DIM+R_DIM) // 768
#define RG 128                 // persistent CTAs for recurrence
#define SENT 0x7FC00001u       // NaN-payload sentinel; real h in (-1,1) never equals it
#define RT 384                 // recurrence threads: 8 GEMV warps + 4 poller warps

// ---------------- static scratch (allocation-free rule) ----------------
__device__ float d_X[(size_t)S_LEN*GATE_W];       // precomputed x-gates + bias
__device__ float d_Hs[(size_t)S_LEN*H_DIM];       // word-LSTM hidden states (sentinel-filled)
__device__ float d_gates[(size_t)S_LEN*4*R_DIM];  // char-LSTM gate scratch
__device__ float d_xcat[(size_t)S_LEN*XCAT_DIM];  // [embed | char_rep]
__device__ float d_hchar[(size_t)S_LEN*R_DIM];
__device__ float d_cchar[(size_t)S_LEN*R_DIM];

__device__ __forceinline__ float sigmf(float x){ return 1.f/(1.f+__expf(-x)); }
__device__ __forceinline__ float tanh_fast(float x){
    float e = __expf(-2.f*x);                  // overflow-safe: e=inf -> -1, e=0 -> 1
    return __fdividef(2.f, 1.f + e) - 1.f;
}

// packed f32x2 FMA (FFMA2) — PTX-only path, 2 fp32 MACs per issue slot
__device__ __forceinline__ unsigned long long ffma2(
    unsigned long long a, unsigned long long b, unsigned long long c)
{
    unsigned long long d;
    asm("fma.rn.f32x2 %0, %1, %2, %3;" : "=l"(d) : "l"(a), "l"(b), "l"(c));
    return d;
}
__device__ __forceinline__ unsigned long long packf2(float a){
    unsigned long long d;
    unsigned u = __float_as_uint(a);
    asm("mov.b64 %0, {%1, %1};" : "=l"(d) : "r"(u));
    return d;
}

// ---------------- init: sentinel-fill d_Hs, zero char states ----------------
__global__ void init_kernel()
{
    int i = blockIdx.x*blockDim.x + threadIdx.x;
    int nth = gridDim.x*blockDim.x;
    uint4* p = (uint4*)d_Hs;
    int n4 = (S_LEN*H_DIM)/4;
    uint4 sv = make_uint4(SENT,SENT,SENT,SENT);
    for (int k = i; k < n4; k += nth) p[k] = sv;
    int n = S_LEN*R_DIM;
    for (int k = i; k < n; k += nth){
        d_hchar[k] = 0.f;
        d_cchar[k] = 0.f;
    }
}

// ---------------- FFMA2 tiled GEMM: C[M,N] = A[M,K] * B[N,K]^T (+bias[N]) ----------------
// 128x128 CTA tile, 16-deep K panels, 8x8 micro-tile per thread (256 threads).
__global__ __launch_bounds__(256, 2) void sgemm128(
    const float* __restrict__ A, const float* __restrict__ B,
    float* __restrict__ C, const float* __restrict__ bias,
    int M, int N, int K)
{
    __shared__ float As[16][132];
    __shared__ float Bs[16][132];
    const int bm = blockIdx.y*128, bn = blockIdx.x*128;
    const int tid = threadIdx.x;
    const int tx = tid & 15, ty = tid >> 4;
    const int lrow = tid >> 1, lcol = (tid & 1) << 3;

    unsigned long long acc2[8][4];
    #pragma unroll
    for (int i=0;i<8;i++)
        #pragma unroll
        for (int j=0;j<4;j++) acc2[i][j] = 0ull;

    const float* Ag = A + (size_t)(bm+lrow)*K + lcol;
    const float* Bg = B + (size_t)(bn+lrow)*K + lcol;

    for (int k0 = 0; k0 < K; k0 += 16){
        float4 a0 = *(const float4*)(Ag + k0);
        float4 a1 = *(const float4*)(Ag + k0 + 4);
        float4 b0 = *(const float4*)(Bg + k0);
        float4 b1 = *(const float4*)(Bg + k0 + 4);
        As[lcol+0][lrow]=a0.x; As[lcol+1][lrow]=a0.y; As[lcol+2][lrow]=a0.z; As[lcol+3][lrow]=a0.w;
        As[lcol+4][lrow]=a1.x; As[lcol+5][lrow]=a1.y; As[lcol+6][lrow]=a1.z; As[lcol+7][lrow]=a1.w;
        Bs[lcol+0][lrow]=b0.x; Bs[lcol+1][lrow]=b0.y; Bs[lcol+2][lrow]=b0.z; Bs[lcol+3][lrow]=b0.w;
        Bs[lcol+4][lrow]=b1.x; Bs[lcol+5][lrow]=b1.y; Bs[lcol+6][lrow]=b1.z; Bs[lcol+7][lrow]=b1.w;
        __syncthreads();
        #pragma unroll
        for (int kk=0;kk<16;kk++){
            float4 av0 = *(const float4*)&As[kk][ty*8];
            float4 av1 = *(const float4*)&As[kk][ty*8+4];
            float a[8] = {av0.x,av0.y,av0.z,av0.w,av1.x,av1.y,av1.z,av1.w};
            unsigned long long b2[4];
            #pragma unroll
            for (int j=0;j<4;j++){
                float2 bv = *(const float2*)&Bs[kk][tx*2 + 32*j];
                b2[j] = *reinterpret_cast<unsigned long long*>(&bv);
            }
            #pragma unroll
            for (int i=0;i<8;i++){
                unsigned long long aa = packf2(a[i]);
                #pragma unroll
                for (int j=0;j<4;j++)
                    acc2[i][j] = ffma2(aa, b2[j], acc2[i][j]);
            }
        }
        __syncthreads();
    }

    #pragma unroll
    for (int i=0;i<8;i++){
        int row = bm + ty*8 + i;
        #pragma unroll
        for (int j=0;j<4;j++){
            int col = bn + tx*2 + 32*j;
            float2 p = *reinterpret_cast<float2*>(&acc2[i][j]);
            if (bias){ p.x += bias[col]; p.y += bias[col+1]; }
            *(float2*)&C[(size_t)row*N + col] = p;
        }
    }
}

// ---------------- char-LSTM pointwise update (after gates GEMM) ----------------
__global__ __launch_bounds__(256) void char_update(
    const float* __restrict__ chars,
    const float* __restrict__ Wc_ih,
    const float* __restrict__ bc,
    int step)
{
    int idx = blockIdx.x*blockDim.x + threadIdx.x;
    if (idx >= S_LEN*R_DIM) return;
    int r = idx & (R_DIM-1);
    int s = idx >> 8;
    float x = chars[s*C_LEN + step];
    const float* g = d_gates + (size_t)s*4*R_DIM;
    float gi = g[r]           + Wc_ih[r]          *x + bc[r];
    float gf = g[R_DIM+r]     + Wc_ih[R_DIM+r]    *x + bc[R_DIM+r];
    float gg = g[2*R_DIM+r]   + Wc_ih[2*R_DIM+r]  *x + bc[2*R_DIM+r];
    float go = g[3*R_DIM+r]   + Wc_ih[3*R_DIM+r]  *x + bc[3*R_DIM+r];
    float c = d_cchar[idx];
    c = sigmf(gf)*c + sigmf(gi)*tanh_fast(gg);
    d_cchar[idx] = c;
    d_hchar[idx] = sigmf(go)*tanh_fast(c);
}

// ---------------- embed gather + concat with char_rep ----------------
__global__ __launch_bounds__(256) void gather_concat(
    const int* __restrict__ sentence,
    const float* __restrict__ embed)
{
    int idx = blockIdx.x*blockDim.x + threadIdx.x;
    if (idx >= S_LEN*XCAT_DIM) return;
    int c = idx % XCAT_DIM;
    int s = idx / XCAT_DIM;
    d_xcat[idx] = (c < E_DIM)
        ? embed[(size_t)sentence[s]*E_DIM + c]
        : d_hchar[s*R_DIM + (c - E_DIM)];
}

// ---------------- persistent word-LSTM recurrence (R12 + 4 poller warps) ----------------
// 128 CTAs x 384 threads. Warps 0-7: GEMV+epilogue for h unit (cta*8+w), weights
// in regs. Warps 8-11: pollers, each lane owns 2 chunks, SERIALIZED load-test-
// store sweep (scoreboard-paced probing — the validated rate limiter). Halving
// chunks-per-lane halves worst-case detection latency (1040 -> ~520 cyc) at
// ~1000 B/cyc chip-wide poll traffic (16% of LTS cap).
__global__ __launch_bounds__(RT, 1) void word_recur(const float* __restrict__ Whh)
{
    const int cta  = blockIdx.x;
    const int w    = threadIdx.x >> 5;
    const int lane = threadIdx.x & 31;

    __shared__ float hsm[2][H_DIM];   // parity double-buffered h

    for (int i = threadIdx.x; i < H_DIM; i += RT) hsm[0][i] = 0.f;  // h(-1)=0

    // GEMV warps: weights for rows j_g = g*H_DIM + cta*8 + w
    ulonglong2 wq[4][8];
    float xv[4] = {0.f,0.f,0.f,0.f};
    float cstate = 0.f;
    if (w < 8){
        #pragma unroll
        for (int g=0; g<4; g++){
            const ulonglong2* W = (const ulonglong2*)(Whh + (size_t)(g*H_DIM + cta*8 + w)*H_DIM);
            #pragma unroll
            for (int i=0;i<8;i++) wq[g][i] = W[lane + 32*i];
        }
        if (lane == 0){
            #pragma unroll
            for (int g=0; g<4; g++) xv[g] = d_X[g*H_DIM + cta*8 + w];
        }
    }
    __syncthreads();

    for (int t = 0; t < S_LEN; t++){
        if (w < 8){
            // ---- GEMV over hsm[t&1] ----
            const float4* h4 = (const float4*)hsm[t & 1];
            unsigned long long accA[4] = {0ull,0ull,0ull,0ull};
            unsigned long long accB[4] = {0ull,0ull,0ull,0ull};
            #pragma unroll
            for (int i=0;i<8;i++){
                float4 hv4 = h4[lane + 32*i];
                ulonglong2 hu = *reinterpret_cast<ulonglong2*>(&hv4);
                #pragma unroll
                for (int g=0; g<4; g++){
                    accA[g] = ffma2(hu.x, wq[g][i].x, accA[g]);
                    accB[g] = ffma2(hu.y, wq[g][i].y, accB[g]);
                }
            }
            float s[4];
            #pragma unroll
            for (int g=0; g<4; g++){
                float2 fa = *reinterpret_cast<float2*>(&accA[g]);
                float2 fb = *reinterpret_cast<float2*>(&accB[g]);
                s[g] = (fa.x + fa.y) + (fb.x + fb.y);
            }
            #pragma unroll
            for (int m=16;m>0;m>>=1){
                #pragma unroll
                for (int g=0; g<4; g++)
                    s[g] += __shfl_down_sync(0xffffffffu, s[g], m);
            }
            // ---- epilogue + publish (lane 0): the h store IS the flag ----
            if (lane == 0){
                float gi = s[0]+xv[0], gf = s[1]+xv[1], gg = s[2]+xv[2], go = s[3]+xv[3];
                float c = sigmf(gf)*cstate + sigmf(gi)*tanh_fast(gg);
                cstate = c;
                float hv = sigmf(go)*tanh_fast(c);
                float* dst = d_Hs + (size_t)t*H_DIM + cta*8 + w;
                asm volatile("st.global.cg.f32 [%0], %1;" :: "l"(dst), "f"(hv) : "memory");
                if (t + 1 < S_LEN){
                    #pragma unroll
                    for (int g=0; g<4; g++)
                        xv[g] = __ldcs(&d_X[(size_t)(t+1)*GATE_W + g*H_DIM + cta*8 + w]);
                }
            }
        } else {
            // ---- pollers (warps 8-11): SERIALIZED sweep, 2 chunks per lane ----
            const int pw = w - 8;                     // 0..3, each covers 64 uint4
            const uint4* hrow = (const uint4*)(d_Hs + (size_t)t*H_DIM);
            uint4* dst4 = (uint4*)hsm[(t+1) & 1];
            unsigned pend = 0x3u;                     // 2 chunks of 16B per lane
            do {
                #pragma unroll
                for (int k = 0; k < 2; k++){
                    if (pend & (1u<<k)){
                        int idx = pw*64 + k*32 + lane;
                        uint4 v;
                        asm volatile("ld.global.cg.v4.u32 {%0,%1,%2,%3}, [%4];"
                            : "=r"(v.x), "=r"(v.y), "=r"(v.z), "=r"(v.w)
                            : "l"(hrow + idx) : "memory");
                        if (v.x != SENT && v.y != SENT && v.z != SENT && v.w != SENT){
                            dst4[idx] = v;
                            pend &= ~(1u<<k);
                        }
                    }
                }
            } while (__ballot_sync(0xffffffffu, pend != 0u));
        }
        __syncthreads();   // hsm[(t+1)&1] complete
    }
}

// ---------------- output layer + log_softmax ----------------
__global__ __launch_bounds__(128) void out_kernel(
    const float* __restrict__ Wout,
    const float* __restrict__ bout,
    float* __restrict__ out)
{
    int s = blockIdx.x;
    __shared__ float hrow[H_DIM];
    __shared__ float e[64];
    __shared__ float s_lse;
    int tid = threadIdx.x;

    const float4* Hs4 = (const float4*)(d_Hs + (size_t)s*H_DIM);
    ((float4*)hrow)[tid*2]   = Hs4[tid*2];
    ((float4*)hrow)[tid*2+1] = Hs4[tid*2+1];
    __syncthreads();

    int warp = tid >> 5, lane = tid & 31;
    for (int l = warp; l < L_DIM; l += 4){
        const float* wr = Wout + (size_t)l*H_DIM;
        float sum = 0.f;
        for (int k = lane; k < H_DIM; k += 32) sum = fmaf(hrow[k], wr[k], sum);
        #pragma unroll
        for (int m=16;m>0;m>>=1) sum += __shfl_xor_sync(0xffffffffu, sum, m);
        if (lane == 0) e[l] = sum + bout[l];
    }
    __syncthreads();

    if (tid < 32){
        float mx = -1e30f;
        for (int l = tid; l < L_DIM; l += 32) mx = fmaxf(mx, e[l]);
        #pragma unroll
        for (int m=16;m>0;m>>=1) mx = fmaxf(mx, __shfl_xor_sync(0xffffffffu, mx, m));
        float sum = 0.f;
        for (int l = tid; l < L_DIM; l += 32) sum += __expf(e[l]-mx);
        #pragma unroll
        for (int m=16;m>0;m>>=1) sum += __shfl_xor_sync(0xffffffffu, sum, m);
        if (tid == 0) s_lse = mx + logf(sum);
    }
    __syncthreads();

    for (int l = tid; l < L_DIM; l += 128)
        out[(size_t)s*L_DIM + l] = e[l] - s_lse;
}

// ---------------- launch ----------------
extern "C" void kernel_launch(void* const* d_in, const int* in_sizes, int n_in,
                              void* d_out, int out_size)
{
    const int*   sentence = (const int*)  d_in[0];
    const float* chars    = (const float*)d_in[1];
    const float* embed    = (const float*)d_in[2];
    const float* Wc_ih    = (const float*)d_in[3];
    const float* Wc_hh    = (const float*)d_in[4];
    const float* bc       = (const float*)d_in[5];
    const float* Ww_ih    = (const float*)d_in[6];
    const float* Ww_hh    = (const float*)d_in[7];
    const float* bw       = (const float*)d_in[8];
    const float* Wout     = (const float*)d_in[9];
    const float* bout     = (const float*)d_in[10];
    float* out = (float*)d_out;

    float *pX, *pGates, *pXcat, *pHchar;
    cudaGetSymbolAddress((void**)&pX,     d_X);
    cudaGetSymbolAddress((void**)&pGates, d_gates);
    cudaGetSymbolAddress((void**)&pXcat,  d_xcat);
    cudaGetSymbolAddress((void**)&pHchar, d_hchar);

    init_kernel<<<2048, 256>>>();

    // char-level LSTM: gates GEMM (FFMA2) + pointwise, 24 steps
    dim3 gChar(4*R_DIM/128, S_LEN/128);   // (8, 64)
    int pwBlocks = (S_LEN*R_DIM + 255)/256;
    for (int step = 0; step < C_LEN; step++){
        sgemm128<<<gChar, 256>>>(pHchar, Wc_hh, pGates, nullptr,
                                 S_LEN, 4*R_DIM, R_DIM);
        char_update<<<pwBlocks, 256>>>(chars, Wc_ih, bc, step);
    }

    // concat [embed(sentence) | char_rep]
    int gcBlocks = (S_LEN*XCAT_DIM + 255)/256;
    gather_concat<<<gcBlocks, 256>>>(sentence, embed);

    // precompute word-LSTM x-gates: X = xcat @ Ww_ih^T + bw
    dim3 gPre(GATE_W/128, S_LEN/128);     // (32, 64)
    sgemm128<<<gPre, 256>>>(pXcat, Ww_ih, pX, bw,
                            S_LEN, GATE_W, XCAT_DIM);

    // sequential word-LSTM recurrence (serialized poller, 4 poller warps)
    word_recur<<<RG, RT>>>(Ww_hh);

    // output layer + log_softmax
    out_kernel<<<S_LEN, 128>>>(Wout, bout, out);
}